// round 14
// baseline (speedup 1.0000x reference)
#include <cuda_runtime.h>
#include <cuda_fp16.h>
#include <cstdint>

// Problem constants (shapes fixed by the reference).
#define N_NODES   100000
#define N_FEAT    64         // both N_IN and N_OUT
#define N_EDGES_MAX 1600000
#define TILE_ROWS 128        // rows per block in the GEMM
#define SCAN_TILE 1024       // nodes per block in scan phase 1/3
#define NB_MAX    128

// ---- Device-global scratch (allocation-free; zero-initialized at load). ----
__device__ __half g_h[(size_t)N_NODES * N_FEAT];     // h = X@W in fp16 (12.8 MB)
__device__ int    g_cnt[N_NODES];                    // per-dst degree (starts 0;
                                                     // re-zeroed by aggregate)
__device__ int    g_part[N_NODES];                   // block-local excl scan
__device__ int    g_bsums[NB_MAX];                   // scan-tile totals
__device__ int    g_row_start[N_NODES + 1];          // CSR row offsets
__device__ int    g_cursor[N_NODES];                 // fill cursors
__device__ int2   g_perm[N_EDGES_MAX];               // packed {src, val_bits}

// -----------------------------------------------------------------------------
// 1) Histogram of edge_dst (no-return atomics -> REDG path, no warp stall).
// -----------------------------------------------------------------------------
__global__ void hist_kernel(const int* __restrict__ edge_dst, int n_edges)
{
    const int e = blockIdx.x * blockDim.x + threadIdx.x;
    if (e < n_edges) atomicAdd(&g_cnt[edge_dst[e]], 1);
}

// -----------------------------------------------------------------------------
// 2) Per-tile (1024 nodes) exclusive scan of g_cnt; emit tile totals.
// -----------------------------------------------------------------------------
__global__ void __launch_bounds__(256) scan1_kernel(int n)
{
    __shared__ int warp_sums[8];
    const int tid  = threadIdx.x;
    const int lane = tid & 31;
    const int wid  = tid >> 5;
    const int base = blockIdx.x * SCAN_TILE + tid * 4;

    int v0 = (base + 0) < n ? g_cnt[base + 0] : 0;
    int v1 = (base + 1) < n ? g_cnt[base + 1] : 0;
    int v2 = (base + 2) < n ? g_cnt[base + 2] : 0;
    int v3 = (base + 3) < n ? g_cnt[base + 3] : 0;
    const int tsum = v0 + v1 + v2 + v3;

    int x = tsum;                               // inclusive warp scan
    #pragma unroll
    for (int o = 1; o < 32; o <<= 1) {
        int y = __shfl_up_sync(0xFFFFFFFFu, x, o);
        if (lane >= o) x += y;
    }
    if (lane == 31) warp_sums[wid] = x;
    __syncthreads();
    if (wid == 0) {
        int w = lane < 8 ? warp_sums[lane] : 0;
        #pragma unroll
        for (int o = 1; o < 8; o <<= 1) {
            int y = __shfl_up_sync(0xFFFFFFFFu, w, o);
            if (lane >= o) w += y;
        }
        if (lane < 8) warp_sums[lane] = w;
    }
    __syncthreads();

    int excl = x - tsum + (wid > 0 ? warp_sums[wid - 1] : 0);
    if ((base + 0) < n) g_part[base + 0] = excl; excl += v0;
    if ((base + 1) < n) g_part[base + 1] = excl; excl += v1;
    if ((base + 2) < n) g_part[base + 2] = excl; excl += v2;
    if ((base + 3) < n) g_part[base + 3] = excl;

    if (tid == 255) g_bsums[blockIdx.x] = warp_sums[7];   // tile total
}

// -----------------------------------------------------------------------------
// 3) row_start = part + prefix(bsums);  cursor = row_start.
//    Each block computes its own bsums prefix (<=128 L2-hit loads).
// -----------------------------------------------------------------------------
__global__ void __launch_bounds__(256) scan3_kernel(int n, int n_edges)
{
    __shared__ int warp_sums[8];
    __shared__ int s_pref;
    const int t = threadIdx.x;

    int v = (t < (int)blockIdx.x) ? g_bsums[t] : 0;     // blockIdx.x < NB_MAX
    #pragma unroll
    for (int o = 16; o; o >>= 1) v += __shfl_down_sync(0xFFFFFFFFu, v, o);
    if ((t & 31) == 0) warp_sums[t >> 5] = v;
    __syncthreads();
    if (t == 0) {
        int s = 0;
        #pragma unroll
        for (int w = 0; w < 8; ++w) s += warp_sums[w];
        s_pref = s;
    }
    __syncthreads();
    const int pref = s_pref;

    #pragma unroll
    for (int k = 0; k < 4; ++k) {
        const int i = blockIdx.x * SCAN_TILE + k * 256 + t;
        if (i < n) {
            const int rs = g_part[i] + pref;
            g_row_start[i] = rs;
            g_cursor[i]    = rs;
        }
    }
    if (blockIdx.x == 0 && t == 0) g_row_start[n] = n_edges;
}

// -----------------------------------------------------------------------------
// 4a) Lean standalone fill: counting-sort edges into per-dst CSR slots.
//     No smem -> full occupancy; 32 warps/SM hide the cursor-ATOMG latency.
// -----------------------------------------------------------------------------
__global__ void __launch_bounds__(256) fill_kernel(
    const int*   __restrict__ edge_src,
    const int*   __restrict__ edge_dst,
    const float* __restrict__ edge_val,
    int n_edges)
{
    const int e = blockIdx.x * blockDim.x + threadIdx.x;
    if (e >= n_edges) return;
    const int d   = edge_dst[e];
    const int pos = atomicAdd(&g_cursor[d], 1);
    g_perm[pos] = make_int2(edge_src[e], __float_as_int(edge_val[e]));
}

// -----------------------------------------------------------------------------
// 4b) GEMM: h = X @ W (R7 tiling), fp16 store.
// -----------------------------------------------------------------------------
__global__ void __launch_bounds__(256) gemm_kernel(
    const float* __restrict__ X, const float* __restrict__ W, int n_nodes)
{
    __shared__ float Xs[TILE_ROWS][N_FEAT];   // 32 KB
    __shared__ float Ws[N_FEAT][N_FEAT];      // 16 KB

    const int tid  = threadIdx.x;
    const int cg   = tid & 15;    // cols cg*4 .. cg*4+3
    const int rgrp = tid >> 4;    // rows rgrp*8 .. rgrp*8+7
    const int base = blockIdx.x * TILE_ROWS;

    {
        const float4* Wv  = reinterpret_cast<const float4*>(W);
        float4*       Wsv = reinterpret_cast<float4*>(Ws);
        #pragma unroll
        for (int i = 0; i < 4; ++i)
            Wsv[tid + i * 256] = Wv[tid + i * 256];
    }
    {
        const float4* Xv  = reinterpret_cast<const float4*>(X);
        float4*       Xsv = reinterpret_cast<float4*>(Xs);
        #pragma unroll
        for (int i = 0; i < 8; ++i) {
            const int idx = tid + i * 256;
            const int row = base + (idx >> 4);
            const int src = row < n_nodes ? row : (n_nodes - 1);
            Xsv[idx] = Xv[(size_t)src * 16 + (idx & 15)];
        }
    }
    __syncthreads();

    float acc[8][4];
    #pragma unroll
    for (int i = 0; i < 8; ++i)
        #pragma unroll
        for (int c = 0; c < 4; ++c)
            acc[i][c] = 0.0f;

    #pragma unroll 2
    for (int k4 = 0; k4 < N_FEAT / 4; ++k4) {
        float4 wv[4];
        #pragma unroll
        for (int j = 0; j < 4; ++j)
            wv[j] = *reinterpret_cast<const float4*>(&Ws[k4 * 4 + j][cg * 4]);

        #pragma unroll
        for (int i = 0; i < 8; ++i) {
            const float4 xv =
                *reinterpret_cast<const float4*>(&Xs[rgrp * 8 + i][k4 * 4]);
            #pragma unroll
            for (int c = 0; c < 4; ++c) {
                acc[i][c] = fmaf(xv.x, (&wv[0].x)[c], acc[i][c]);
                acc[i][c] = fmaf(xv.y, (&wv[1].x)[c], acc[i][c]);
                acc[i][c] = fmaf(xv.z, (&wv[2].x)[c], acc[i][c]);
                acc[i][c] = fmaf(xv.w, (&wv[3].x)[c], acc[i][c]);
            }
        }
    }

    // fp16 store: 4 cols -> 2x half2 = 8B per row; 16 lanes = 128B coalesced.
    #pragma unroll
    for (int i = 0; i < 8; ++i) {
        const int row = base + rgrp * 8 + i;
        if (row < n_nodes) {
            const __half2 h01 = __floats2half2_rn(acc[i][0], acc[i][1]);
            const __half2 h23 = __floats2half2_rn(acc[i][2], acc[i][3]);
            uint2 o;
            o.x = *reinterpret_cast<const unsigned*>(&h01);
            o.y = *reinterpret_cast<const unsigned*>(&h23);
            reinterpret_cast<uint2*>(g_h)[(size_t)row * 16 + cg] = o;
        }
    }
}

// -----------------------------------------------------------------------------
// 5) Pull aggregation + fused ReLU. 16 lanes per node; each lane gathers 8B
//    (4 halves) per edge, accumulates in fp32, writes 16B of out.
//    Re-zeros g_cnt[node] so the next execution's histogram starts clean.
// -----------------------------------------------------------------------------
__global__ void __launch_bounds__(256) aggregate_kernel(
    float* __restrict__ out, int n_nodes)
{
    const int t    = blockIdx.x * blockDim.x + threadIdx.x;
    const int node = t >> 4;
    const int lane = t & 15;
    if (node >= n_nodes) return;

    if (lane == 0) g_cnt[node] = 0;     // restore invariant for next execution

    const int start = g_row_start[node];
    const int end   = g_row_start[node + 1];
    const uint2* Hv = reinterpret_cast<const uint2*>(g_h);   // 4 halves per uint2

    float4 acc = make_float4(0.0f, 0.0f, 0.0f, 0.0f);

    int e = start;
    for (; e + 1 < end; e += 2) {                 // 2-way for MLP
        const int2 p0 = g_perm[e];
        const int2 p1 = g_perm[e + 1];
        const uint2 q0 = Hv[(size_t)p0.x * 16 + lane];
        const uint2 q1 = Hv[(size_t)p1.x * 16 + lane];
        const float v0 = __int_as_float(p0.y);
        const float v1 = __int_as_float(p1.y);
        const float2 a0 = __half22float2(*reinterpret_cast<const __half2*>(&q0.x));
        const float2 a1 = __half22float2(*reinterpret_cast<const __half2*>(&q0.y));
        const float2 b0 = __half22float2(*reinterpret_cast<const __half2*>(&q1.x));
        const float2 b1 = __half22float2(*reinterpret_cast<const __half2*>(&q1.y));
        acc.x = fmaf(a0.x, v0, acc.x);  acc.y = fmaf(a0.y, v0, acc.y);
        acc.z = fmaf(a1.x, v0, acc.z);  acc.w = fmaf(a1.y, v0, acc.w);
        acc.x = fmaf(b0.x, v1, acc.x);  acc.y = fmaf(b0.y, v1, acc.y);
        acc.z = fmaf(b1.x, v1, acc.z);  acc.w = fmaf(b1.y, v1, acc.w);
    }
    if (e < end) {
        const int2 p = g_perm[e];
        const uint2 q = Hv[(size_t)p.x * 16 + lane];
        const float v = __int_as_float(p.y);
        const float2 a0 = __half22float2(*reinterpret_cast<const __half2*>(&q.x));
        const float2 a1 = __half22float2(*reinterpret_cast<const __half2*>(&q.y));
        acc.x = fmaf(a0.x, v, acc.x);  acc.y = fmaf(a0.y, v, acc.y);
        acc.z = fmaf(a1.x, v, acc.z);  acc.w = fmaf(a1.y, v, acc.w);
    }

    acc.x = fmaxf(acc.x, 0.0f);
    acc.y = fmaxf(acc.y, 0.0f);
    acc.z = fmaxf(acc.z, 0.0f);
    acc.w = fmaxf(acc.w, 0.0f);
    reinterpret_cast<float4*>(out)[(size_t)node * 16 + lane] = acc;
}

// -----------------------------------------------------------------------------
// Launch: hist -> scan1 -> scan3 -> fill -> gemm -> aggregate.
// 6 lean launches, single stream, graph-capturable.
// Input order (metadata): X, W, edge_val, edge_src, edge_dst.
// -----------------------------------------------------------------------------
extern "C" void kernel_launch(void* const* d_in, const int* in_sizes, int n_in,
                              void* d_out, int out_size)
{
    const float* X        = (const float*)d_in[0];
    const float* W        = (const float*)d_in[1];
    const float* edge_val = (const float*)d_in[2];
    const int*   edge_src = (const int*)  d_in[3];
    const int*   edge_dst = (const int*)  d_in[4];
    float*       out      = (float*)d_out;

    const int n_nodes = in_sizes[0] / N_FEAT;   // 100000
    const int n_edges = in_sizes[2];            // 1600000
    const int nb      = (n_nodes + SCAN_TILE - 1) / SCAN_TILE;   // 98
    const int gE      = (n_edges + 255) / 256;                   // 6250
    const int gGemm   = (n_nodes + TILE_ROWS - 1) / TILE_ROWS;   // 782

    hist_kernel<<<gE, 256>>>(edge_dst, n_edges);
    scan1_kernel<<<nb, 256>>>(n_nodes);
    scan3_kernel<<<nb, 256>>>(n_nodes, n_edges);
    fill_kernel<<<gE, 256>>>(edge_src, edge_dst, edge_val, n_edges);
    gemm_kernel<<<gGemm, 256>>>(X, W, n_nodes);
    {
        const long long total = (long long)n_nodes * 16;
        const int grid = (int)((total + 255) / 256);
        aggregate_kernel<<<grid, 256>>>(out, n_nodes);
    }
}

// round 15
// speedup vs baseline: 1.3797x; 1.3797x over previous
#include <cuda_runtime.h>
#include <cuda_fp16.h>
#include <cstdint>

// Problem constants (shapes fixed by the reference).
#define N_NODES   100000
#define N_FEAT    64         // both N_IN and N_OUT
#define N_EDGES_MAX 1600000
#define TILE_ROWS 128        // rows per block in the GEMM
#define SCAN_TILE 1024       // nodes per block in scan phase 1/3
#define NB_MAX    128

// ---- Device-global scratch (allocation-free; zero-initialized at load). ----
__device__ __half g_h[(size_t)N_NODES * N_FEAT];     // h = X@W in fp16 (12.8 MB)
__device__ int    g_cnt[N_NODES];                    // per-dst degree (starts 0;
                                                     // re-zeroed by aggregate)
__device__ int    g_part[N_NODES];                   // block-local excl scan
__device__ int    g_bsums[NB_MAX];                   // scan-tile totals
__device__ int    g_row_start[N_NODES + 1];          // CSR row offsets
__device__ int    g_cursor[N_NODES];                 // fill cursors
__device__ int2   g_perm[N_EDGES_MAX];               // packed {src, val_bits}

// -----------------------------------------------------------------------------
// 1) Histogram of edge_dst (no-return atomics -> REDG path, no warp stall).
// -----------------------------------------------------------------------------
__global__ void hist_kernel(const int* __restrict__ edge_dst, int n_edges)
{
    const int e = blockIdx.x * blockDim.x + threadIdx.x;
    if (e < n_edges) atomicAdd(&g_cnt[edge_dst[e]], 1);
}

// -----------------------------------------------------------------------------
// 2) Per-tile (1024 nodes) exclusive scan of g_cnt; emit tile totals.
// -----------------------------------------------------------------------------
__global__ void __launch_bounds__(256) scan1_kernel(int n)
{
    __shared__ int warp_sums[8];
    const int tid  = threadIdx.x;
    const int lane = tid & 31;
    const int wid  = tid >> 5;
    const int base = blockIdx.x * SCAN_TILE + tid * 4;

    int v0 = (base + 0) < n ? g_cnt[base + 0] : 0;
    int v1 = (base + 1) < n ? g_cnt[base + 1] : 0;
    int v2 = (base + 2) < n ? g_cnt[base + 2] : 0;
    int v3 = (base + 3) < n ? g_cnt[base + 3] : 0;
    const int tsum = v0 + v1 + v2 + v3;

    int x = tsum;                               // inclusive warp scan
    #pragma unroll
    for (int o = 1; o < 32; o <<= 1) {
        int y = __shfl_up_sync(0xFFFFFFFFu, x, o);
        if (lane >= o) x += y;
    }
    if (lane == 31) warp_sums[wid] = x;
    __syncthreads();
    if (wid == 0) {
        int w = lane < 8 ? warp_sums[lane] : 0;
        #pragma unroll
        for (int o = 1; o < 8; o <<= 1) {
            int y = __shfl_up_sync(0xFFFFFFFFu, w, o);
            if (lane >= o) w += y;
        }
        if (lane < 8) warp_sums[lane] = w;
    }
    __syncthreads();

    int excl = x - tsum + (wid > 0 ? warp_sums[wid - 1] : 0);
    if ((base + 0) < n) g_part[base + 0] = excl; excl += v0;
    if ((base + 1) < n) g_part[base + 1] = excl; excl += v1;
    if ((base + 2) < n) g_part[base + 2] = excl; excl += v2;
    if ((base + 3) < n) g_part[base + 3] = excl;

    if (tid == 255) g_bsums[blockIdx.x] = warp_sums[7];   // tile total
}

// -----------------------------------------------------------------------------
// 3) row_start = part + prefix(bsums);  cursor = row_start.
//    Each block computes its own bsums prefix (<=128 L2-hit loads).
// -----------------------------------------------------------------------------
__global__ void __launch_bounds__(256) scan3_kernel(int n, int n_edges)
{
    __shared__ int warp_sums[8];
    __shared__ int s_pref;
    const int t = threadIdx.x;

    int v = (t < (int)blockIdx.x) ? g_bsums[t] : 0;     // blockIdx.x < NB_MAX
    #pragma unroll
    for (int o = 16; o; o >>= 1) v += __shfl_down_sync(0xFFFFFFFFu, v, o);
    if ((t & 31) == 0) warp_sums[t >> 5] = v;
    __syncthreads();
    if (t == 0) {
        int s = 0;
        #pragma unroll
        for (int w = 0; w < 8; ++w) s += warp_sums[w];
        s_pref = s;
    }
    __syncthreads();
    const int pref = s_pref;

    #pragma unroll
    for (int k = 0; k < 4; ++k) {
        const int i = blockIdx.x * SCAN_TILE + k * 256 + t;
        if (i < n) {
            const int rs = g_part[i] + pref;
            g_row_start[i] = rs;
            g_cursor[i]    = rs;
        }
    }
    if (blockIdx.x == 0 && t == 0) g_row_start[n] = n_edges;
}

// -----------------------------------------------------------------------------
// 4) FUSED gemm + fill-tail. Every block: (a) gemm its 128-row tile (R7
//    tiling, fp16 store), then (b) counting-sort a contiguous ~2K-edge chunk.
//    Blocks finish gemm at staggered times, so fill's ATOMG latency hides
//    behind other blocks' FMA issue instead of occupying dedicated waves.
// -----------------------------------------------------------------------------
__global__ void __launch_bounds__(256) gemm_fill_kernel(
    const float* __restrict__ X, const float* __restrict__ W,
    const int*   __restrict__ edge_src,
    const int*   __restrict__ edge_dst,
    const float* __restrict__ edge_val,
    int n_nodes, int n_edges, int edges_per_block)
{
    __shared__ float Xs[TILE_ROWS][N_FEAT];   // 32 KB
    __shared__ float Ws[N_FEAT][N_FEAT];      // 16 KB

    const int tid  = threadIdx.x;
    const int cg   = tid & 15;    // cols cg*4 .. cg*4+3
    const int rgrp = tid >> 4;    // rows rgrp*8 .. rgrp*8+7
    const int base = blockIdx.x * TILE_ROWS;

    // ---- gemm phase ----
    {
        const float4* Wv  = reinterpret_cast<const float4*>(W);
        float4*       Wsv = reinterpret_cast<float4*>(Ws);
        #pragma unroll
        for (int i = 0; i < 4; ++i)
            Wsv[tid + i * 256] = Wv[tid + i * 256];
    }
    {
        const float4* Xv  = reinterpret_cast<const float4*>(X);
        float4*       Xsv = reinterpret_cast<float4*>(Xs);
        #pragma unroll
        for (int i = 0; i < 8; ++i) {
            const int idx = tid + i * 256;
            const int row = base + (idx >> 4);
            const int src = row < n_nodes ? row : (n_nodes - 1);
            Xsv[idx] = Xv[(size_t)src * 16 + (idx & 15)];
        }
    }
    __syncthreads();

    float acc[8][4];
    #pragma unroll
    for (int i = 0; i < 8; ++i)
        #pragma unroll
        for (int c = 0; c < 4; ++c)
            acc[i][c] = 0.0f;

    #pragma unroll 2
    for (int k4 = 0; k4 < N_FEAT / 4; ++k4) {
        float4 wv[4];
        #pragma unroll
        for (int j = 0; j < 4; ++j)
            wv[j] = *reinterpret_cast<const float4*>(&Ws[k4 * 4 + j][cg * 4]);

        #pragma unroll
        for (int i = 0; i < 8; ++i) {
            const float4 xv =
                *reinterpret_cast<const float4*>(&Xs[rgrp * 8 + i][k4 * 4]);
            #pragma unroll
            for (int c = 0; c < 4; ++c) {
                acc[i][c] = fmaf(xv.x, (&wv[0].x)[c], acc[i][c]);
                acc[i][c] = fmaf(xv.y, (&wv[1].x)[c], acc[i][c]);
                acc[i][c] = fmaf(xv.z, (&wv[2].x)[c], acc[i][c]);
                acc[i][c] = fmaf(xv.w, (&wv[3].x)[c], acc[i][c]);
            }
        }
    }

    // fp16 store: 4 cols -> 2x half2 = 8B per row; 16 lanes = 128B coalesced.
    #pragma unroll
    for (int i = 0; i < 8; ++i) {
        const int row = base + rgrp * 8 + i;
        if (row < n_nodes) {
            const __half2 h01 = __floats2half2_rn(acc[i][0], acc[i][1]);
            const __half2 h23 = __floats2half2_rn(acc[i][2], acc[i][3]);
            uint2 o;
            o.x = *reinterpret_cast<const unsigned*>(&h01);
            o.y = *reinterpret_cast<const unsigned*>(&h23);
            reinterpret_cast<uint2*>(g_h)[(size_t)row * 16 + cg] = o;
        }
    }

    // ---- fill tail: this block's contiguous edge chunk (no sync needed) ----
    const int e0   = blockIdx.x * edges_per_block;
    const int eEnd = min(e0 + edges_per_block, n_edges);
    for (int e = e0 + tid; e < eEnd; e += 256) {
        const int d   = edge_dst[e];
        const int pos = atomicAdd(&g_cursor[d], 1);
        g_perm[pos] = make_int2(edge_src[e], __float_as_int(edge_val[e]));
    }
}

// -----------------------------------------------------------------------------
// 5) Pull aggregation + fused ReLU. 16 lanes per node; each lane gathers 8B
//    (4 halves) per edge, accumulates in fp32, writes 16B of out.
//    Re-zeros g_cnt[node] so the next execution's histogram starts clean.
// -----------------------------------------------------------------------------
__global__ void __launch_bounds__(256) aggregate_kernel(
    float* __restrict__ out, int n_nodes)
{
    const int t    = blockIdx.x * blockDim.x + threadIdx.x;
    const int node = t >> 4;
    const int lane = t & 15;
    if (node >= n_nodes) return;

    if (lane == 0) g_cnt[node] = 0;     // restore invariant for next execution

    const int start = g_row_start[node];
    const int end   = g_row_start[node + 1];
    const uint2* Hv = reinterpret_cast<const uint2*>(g_h);   // 4 halves per uint2

    float4 acc = make_float4(0.0f, 0.0f, 0.0f, 0.0f);

    int e = start;
    for (; e + 1 < end; e += 2) {                 // 2-way for MLP
        const int2 p0 = g_perm[e];
        const int2 p1 = g_perm[e + 1];
        const uint2 q0 = Hv[(size_t)p0.x * 16 + lane];
        const uint2 q1 = Hv[(size_t)p1.x * 16 + lane];
        const float v0 = __int_as_float(p0.y);
        const float v1 = __int_as_float(p1.y);
        const float2 a0 = __half22float2(*reinterpret_cast<const __half2*>(&q0.x));
        const float2 a1 = __half22float2(*reinterpret_cast<const __half2*>(&q0.y));
        const float2 b0 = __half22float2(*reinterpret_cast<const __half2*>(&q1.x));
        const float2 b1 = __half22float2(*reinterpret_cast<const __half2*>(&q1.y));
        acc.x = fmaf(a0.x, v0, acc.x);  acc.y = fmaf(a0.y, v0, acc.y);
        acc.z = fmaf(a1.x, v0, acc.z);  acc.w = fmaf(a1.y, v0, acc.w);
        acc.x = fmaf(b0.x, v1, acc.x);  acc.y = fmaf(b0.y, v1, acc.y);
        acc.z = fmaf(b1.x, v1, acc.z);  acc.w = fmaf(b1.y, v1, acc.w);
    }
    if (e < end) {
        const int2 p = g_perm[e];
        const uint2 q = Hv[(size_t)p.x * 16 + lane];
        const float v = __int_as_float(p.y);
        const float2 a0 = __half22float2(*reinterpret_cast<const __half2*>(&q.x));
        const float2 a1 = __half22float2(*reinterpret_cast<const __half2*>(&q.y));
        acc.x = fmaf(a0.x, v, acc.x);  acc.y = fmaf(a0.y, v, acc.y);
        acc.z = fmaf(a1.x, v, acc.z);  acc.w = fmaf(a1.y, v, acc.w);
    }

    acc.x = fmaxf(acc.x, 0.0f);
    acc.y = fmaxf(acc.y, 0.0f);
    acc.z = fmaxf(acc.z, 0.0f);
    acc.w = fmaxf(acc.w, 0.0f);
    reinterpret_cast<float4*>(out)[(size_t)node * 16 + lane] = acc;
}

// -----------------------------------------------------------------------------
// Launch: hist -> scan1 -> scan3 -> fused(gemm+fill-tail) -> aggregate.
// 5 launches, single stream, graph-capturable.
// Input order (metadata): X, W, edge_val, edge_src, edge_dst.
// -----------------------------------------------------------------------------
extern "C" void kernel_launch(void* const* d_in, const int* in_sizes, int n_in,
                              void* d_out, int out_size)
{
    const float* X        = (const float*)d_in[0];
    const float* W        = (const float*)d_in[1];
    const float* edge_val = (const float*)d_in[2];
    const int*   edge_src = (const int*)  d_in[3];
    const int*   edge_dst = (const int*)  d_in[4];
    float*       out      = (float*)d_out;

    const int n_nodes = in_sizes[0] / N_FEAT;   // 100000
    const int n_edges = in_sizes[2];            // 1600000
    const int nb      = (n_nodes + SCAN_TILE - 1) / SCAN_TILE;   // 98
    const int gE      = (n_edges + 255) / 256;                   // 6250
    const int gGemm   = (n_nodes + TILE_ROWS - 1) / TILE_ROWS;   // 782
    const int epb     = (n_edges + gGemm - 1) / gGemm;           // ~2047

    hist_kernel<<<gE, 256>>>(edge_dst, n_edges);
    scan1_kernel<<<nb, 256>>>(n_nodes);
    scan3_kernel<<<nb, 256>>>(n_nodes, n_edges);
    gemm_fill_kernel<<<gGemm, 256>>>(X, W, edge_src, edge_dst, edge_val,
                                     n_nodes, n_edges, epb);
    {
        const long long total = (long long)n_nodes * 16;
        const int grid = (int)((total + 255) / 256);
        aggregate_kernel<<<grid, 256>>>(out, n_nodes);
    }
}